// round 7
// baseline (speedup 1.0000x reference)
#include <cuda_runtime.h>
#include <math.h>

#define NMAX 50000
#define EMAX 600000
#define F    128
#define NCLSK 40
#define BN_EPS 1e-5f

typedef unsigned long long u64;

__device__ __forceinline__ u64 pack_dup(float a) {
    u64 r;
    asm("mov.b64 %0, {%1, %1};" : "=l"(r) : "f"(a));
    return r;
}
__device__ __forceinline__ void ffma2(u64 &d, u64 a, u64 b) {
    asm("fma.rn.f32x2 %0, %1, %2, %0;" : "+l"(d) : "l"(a), "l"(b));
}
__device__ __forceinline__ float2 unpack2(u64 v) {
    float lo, hi;
    asm("mov.b64 {%0, %1}, %2;" : "=f"(lo), "=f"(hi) : "l"(v));
    return make_float2(lo, hi);
}

// ---------------- scratch (device globals; no allocation allowed) ----------------
__device__ float  g_hlin0[NMAX * F];
__device__ float  g_hlin1[NMAX * F];
__device__ int    g_deg [NMAX];
__device__ int    g_off [NMAX];
__device__ int    g_cur [NMAX];
__device__ int    g_csrc[EMAX];
__device__ float  g_invdeg[NMAX];
__device__ float  g_stats[4 * F];   // layer0: [0..255], layer1: [256..511]
__device__ int    g_counter;

// ---------------- histogram (+ zero stats/counter piggyback) ----------------
__global__ void hist_kernel(const int* __restrict__ ei, int ne, int n) {
    if (blockIdx.x == 0) {
        g_stats[threadIdx.x] = 0.f;
        g_stats[256 + threadIdx.x] = 0.f;
        if (threadIdx.x == 0) g_counter = 0;
    }
    int e = blockIdx.x * blockDim.x + threadIdx.x;
    if (e < ne) {
        int d = ei[ne + e];
        if ((unsigned)d < (unsigned)n) atomicAdd(&g_deg[d], 1);
    }
}

// ---------------- one-pass block scan with atomic base ----------------
__global__ __launch_bounds__(256) void scan_blocks_kernel(int n) {
    int tid = threadIdx.x;
    int i = blockIdx.x * 256 + tid;
    int v = (i < n) ? g_deg[i] : 0;

    int incl = v;
    #pragma unroll
    for (int o = 1; o < 32; o <<= 1) {
        int t = __shfl_up_sync(0xffffffffu, incl, o);
        if ((tid & 31) >= o) incl += t;
    }
    __shared__ int wsum[8];
    if ((tid & 31) == 31) wsum[tid >> 5] = incl;
    __syncthreads();
    if (tid < 8) {
        int w = wsum[tid];
        int s = w;
        #pragma unroll
        for (int o = 1; o < 8; o <<= 1) {
            int t = __shfl_up_sync(0x000000ffu, s, o);
            if (tid >= o) s += t;
        }
        wsum[tid] = s - w;
    }
    __syncthreads();
    incl += wsum[tid >> 5];

    __shared__ int base_s;
    if (tid == 255) base_s = atomicAdd(&g_counter, incl);
    __syncthreads();

    if (i < n) {
        int off = base_s + incl - v;
        g_off[i] = off;
        g_cur[i] = off;
        g_invdeg[i] = 1.0f / fmaxf((float)v, 1.0f);
    }
}

__global__ void fill_kernel(const int* __restrict__ ei, int ne, int n) {
    int e = blockIdx.x * blockDim.x + threadIdx.x;
    if (e < ne) {
        int d = ei[ne + e];
        int s = ei[e];
        if ((unsigned)d < (unsigned)n && (unsigned)s < (unsigned)n) {
            int p = atomicAdd(&g_cur[d], 1);
            g_csrc[p] = s;
        }
    }
}

// ---- fused: gather(+optional BN+ReLU) -> smem -> GEMM + BN-stats epilogue ----
#define FBM 64
#define FPAD 132   // row stride in floats (16B-aligned: 132*4=528)
template<int USE_BN>
__global__ __launch_bounds__(256, 4) void fused_layer_kernel(
        const float* __restrict__ feat,
        const float* __restrict__ W,
        const float* __restrict__ bias,
        float* __restrict__ C,
        float* __restrict__ stats_out,
        const float* __restrict__ stats_in,
        const float* __restrict__ g,
        const float* __restrict__ be,
        int n) {
    __shared__ float As[FBM][FPAD];
    __shared__ float Bs[2][8][F];
    __shared__ float s_sum[F], s_sq[F];
    __shared__ float s_sc[F], s_sh[F];

    int tid = threadIdx.x;
    if (tid < F) {
        s_sum[tid] = 0.f;
        s_sq[tid] = 0.f;
        if (USE_BN) {
            float mean = stats_in[tid] / (float)n;
            float var  = stats_in[F + tid] / (float)n - mean * mean;
            float sck = g[tid] * rsqrtf(var + BN_EPS);
            s_sc[tid] = sck;
            s_sh[tid] = be[tid] - mean * sck;
        }
    }
    if (USE_BN) __syncthreads();

    // ---------- gather phase: 8 warps x 8 nodes ----------
    int wid = tid >> 5, lane = tid & 31;
    int col = lane * 4;
    int base_node = blockIdx.x * FBM;
    float4 sc, sh;
    if (USE_BN) {
        sc = *(const float4*)&s_sc[col];
        sh = *(const float4*)&s_sh[col];
    }
    #pragma unroll
    for (int i = 0; i < FBM / 8; i++) {
        int local = wid * 8 + i;
        int node = base_node + local;
        float4 acc  = make_float4(0.f, 0.f, 0.f, 0.f);
        float4 acc2 = make_float4(0.f, 0.f, 0.f, 0.f);
        if (node < n) {
            int beg = g_off[node];
            int end = beg + g_deg[node];
            int e = beg;
            if (USE_BN) {
                for (; e + 1 < end; e += 2) {
                    int s0 = g_csrc[e], s1 = g_csrc[e + 1];
                    float4 v0 = *(const float4*)(feat + (size_t)s0 * F + col);
                    float4 v1 = *(const float4*)(feat + (size_t)s1 * F + col);
                    acc.x  += fmaxf(v0.x * sc.x + sh.x, 0.f);
                    acc.y  += fmaxf(v0.y * sc.y + sh.y, 0.f);
                    acc.z  += fmaxf(v0.z * sc.z + sh.z, 0.f);
                    acc.w  += fmaxf(v0.w * sc.w + sh.w, 0.f);
                    acc2.x += fmaxf(v1.x * sc.x + sh.x, 0.f);
                    acc2.y += fmaxf(v1.y * sc.y + sh.y, 0.f);
                    acc2.z += fmaxf(v1.z * sc.z + sh.z, 0.f);
                    acc2.w += fmaxf(v1.w * sc.w + sh.w, 0.f);
                }
                if (e < end) {
                    int s0 = g_csrc[e];
                    float4 v0 = *(const float4*)(feat + (size_t)s0 * F + col);
                    acc.x += fmaxf(v0.x * sc.x + sh.x, 0.f);
                    acc.y += fmaxf(v0.y * sc.y + sh.y, 0.f);
                    acc.z += fmaxf(v0.z * sc.z + sh.z, 0.f);
                    acc.w += fmaxf(v0.w * sc.w + sh.w, 0.f);
                }
            } else {
                for (; e + 1 < end; e += 2) {
                    int s0 = g_csrc[e], s1 = g_csrc[e + 1];
                    float4 v0 = *(const float4*)(feat + (size_t)s0 * F + col);
                    float4 v1 = *(const float4*)(feat + (size_t)s1 * F + col);
                    acc.x  += v0.x; acc.y  += v0.y; acc.z  += v0.z; acc.w  += v0.w;
                    acc2.x += v1.x; acc2.y += v1.y; acc2.z += v1.z; acc2.w += v1.w;
                }
                if (e < end) {
                    int s0 = g_csrc[e];
                    float4 v0 = *(const float4*)(feat + (size_t)s0 * F + col);
                    acc.x += v0.x; acc.y += v0.y; acc.z += v0.z; acc.w += v0.w;
                }
            }
            float inv = g_invdeg[node];
            acc.x = (acc.x + acc2.x) * inv;
            acc.y = (acc.y + acc2.y) * inv;
            acc.z = (acc.z + acc2.z) * inv;
            acc.w = (acc.w + acc2.w) * inv;
        }
        *(float4*)&As[local][col] = acc;
    }

    // ---------- GEMM phase: 64x128 tile, A from smem, B streamed ----------
    int tx = tid & 15, ty = tid >> 4;   // 16 col-groups x 8 cols, 16 row-groups x 4 rows
    int b_k   = tid >> 5;
    int b_col = (tid & 31) * 4;

    u64 acc2g[4][4];
    #pragma unroll
    for (int i = 0; i < 4; i++)
        #pragma unroll
        for (int j = 0; j < 4; j++) acc2g[i][j] = 0ULL;

    // prologue: B tile 0
    float4 bv = *(const float4*)(W + (size_t)b_k * F + b_col);
    __syncthreads();   // gather complete + s_sum zero visible
    *(float4*)&Bs[0][b_k][b_col] = bv;
    __syncthreads();

    int buf = 0;
    #pragma unroll
    for (int k0 = 0; k0 < F; k0 += 8) {
        float4 nbv;
        bool more = (k0 + 8) < F;
        if (more) nbv = *(const float4*)(W + (size_t)(k0 + 8 + b_k) * F + b_col);
        #pragma unroll
        for (int kk = 0; kk < 8; kk++) {
            int kg = k0 + kk;
            u64 ra[4];
            ra[0] = pack_dup(As[ty * 4 + 0][kg]);
            ra[1] = pack_dup(As[ty * 4 + 1][kg]);
            ra[2] = pack_dup(As[ty * 4 + 2][kg]);
            ra[3] = pack_dup(As[ty * 4 + 3][kg]);
            ulonglong2 b01 = *(const ulonglong2*)&Bs[buf][kk][tx * 8];
            ulonglong2 b23 = *(const ulonglong2*)&Bs[buf][kk][tx * 8 + 4];
            u64 rb[4] = {b01.x, b01.y, b23.x, b23.y};
            #pragma unroll
            for (int i = 0; i < 4; i++)
                #pragma unroll
                for (int j = 0; j < 4; j++) ffma2(acc2g[i][j], ra[i], rb[j]);
        }
        if (more) {
            int nb = buf ^ 1;
            *(float4*)&Bs[nb][b_k][b_col] = nbv;
        }
        __syncthreads();
        buf ^= 1;
    }

    float bias_r[8];
    #pragma unroll
    for (int j = 0; j < 8; j++) bias_r[j] = __ldg(&bias[tx * 8 + j]);

    float ps[8], pq[8];
    #pragma unroll
    for (int j = 0; j < 8; j++) { ps[j] = 0.f; pq[j] = 0.f; }

    #pragma unroll
    for (int i = 0; i < 4; i++) {
        int r = base_node + ty * 4 + i;
        if (r < n) {
            float va[8];
            #pragma unroll
            for (int jp = 0; jp < 4; jp++) {
                float2 p = unpack2(acc2g[i][jp]);
                va[jp * 2 + 0] = p.x + bias_r[jp * 2 + 0];
                va[jp * 2 + 1] = p.y + bias_r[jp * 2 + 1];
            }
            #pragma unroll
            for (int j = 0; j < 8; j += 4) {
                float4 o = make_float4(va[j], va[j+1], va[j+2], va[j+3]);
                *(float4*)(C + (size_t)r * F + tx * 8 + j) = o;
            }
            #pragma unroll
            for (int j = 0; j < 8; j++) { ps[j] += va[j]; pq[j] += va[j] * va[j]; }
        }
    }
    #pragma unroll
    for (int j = 0; j < 8; j++) {
        atomicAdd(&s_sum[tx * 8 + j], ps[j]);
        atomicAdd(&s_sq[tx * 8 + j], pq[j]);
    }
    __syncthreads();
    if (tid < F) {
        atomicAdd(&stats_out[tid], s_sum[tid]);
        atomicAdd(&stats_out[F + tid], s_sq[tid]);
    }
}

// --- classifier: fused BN(from raw stats)+ReLU + GEMM + log_softmax --------
__global__ __launch_bounds__(256) void classifier_kernel(const float* __restrict__ H,
                                                         const float* __restrict__ Wc,
                                                         const float* __restrict__ bc,
                                                         const float* __restrict__ g,
                                                         const float* __restrict__ be,
                                                         float* __restrict__ outb, int n) {
    __shared__ float sbuf[6656];
    float* As    = sbuf;           // [8][128]  during k-loop
    float* Ws    = sbuf + 1024;    // [128][40]
    float* s_log = sbuf;           // overlay after k-loop: [128][41]
    float* s_lse = sbuf + 5248;    // [128]
    float* s_sc  = sbuf + 6144;    // [128]
    float* s_sh  = sbuf + 6272;    // [128]

    int tid = threadIdx.x;
    int row0 = blockIdx.x * 128;

    if (tid < F) {
        float mean = g_stats[2 * F + tid] / (float)n;
        float var  = g_stats[3 * F + tid] / (float)n - mean * mean;
        float sck = g[tid] * rsqrtf(var + BN_EPS);
        s_sc[tid] = sck;
        s_sh[tid] = be[tid] - mean * sck;
    }
    for (int idx = tid; idx < F * NCLSK; idx += 256) Ws[idx] = Wc[idx];

    int tx = tid & 7;     // 8 col-groups x 5 classes
    int ty = tid >> 3;    // 32 row-groups x 4 rows

    float acc[4][5];
    #pragma unroll
    for (int i = 0; i < 4; i++)
        #pragma unroll
        for (int j = 0; j < 5; j++) acc[i][j] = 0.f;

    int lrow = tid >> 1;
    int seg  = (tid & 1) * 4;
    int grow = row0 + lrow;
    bool rok = grow < n;
    const float* hp = H + (size_t)grow * F;
    __syncthreads();   // s_sc/s_sh + Ws ready

    for (int k0 = 0; k0 < F; k0 += 8) {
        float4 v = make_float4(0.f,0.f,0.f,0.f);
        if (rok) v = *(const float4*)(hp + k0 + seg);
        float4 sc = *(const float4*)&s_sc[k0 + seg];
        float4 sh = *(const float4*)&s_sh[k0 + seg];
        v.x = fmaxf(v.x * sc.x + sh.x, 0.f);
        v.y = fmaxf(v.y * sc.y + sh.y, 0.f);
        v.z = fmaxf(v.z * sc.z + sh.z, 0.f);
        v.w = fmaxf(v.w * sc.w + sh.w, 0.f);
        As[(seg + 0) * 128 + lrow] = v.x;
        As[(seg + 1) * 128 + lrow] = v.y;
        As[(seg + 2) * 128 + lrow] = v.z;
        As[(seg + 3) * 128 + lrow] = v.w;
        __syncthreads();
        #pragma unroll
        for (int kk = 0; kk < 8; kk++) {
            float ra[4], rb[5];
            #pragma unroll
            for (int i = 0; i < 4; i++) ra[i] = As[kk * 128 + ty * 4 + i];
            #pragma unroll
            for (int j = 0; j < 5; j++) rb[j] = Ws[(k0 + kk) * NCLSK + tx * 5 + j];
            #pragma unroll
            for (int i = 0; i < 4; i++)
                #pragma unroll
                for (int j = 0; j < 5; j++) acc[i][j] += ra[i] * rb[j];
        }
        __syncthreads();
    }

    float bias_r[5];
    #pragma unroll
    for (int j = 0; j < 5; j++) bias_r[j] = __ldg(&bc[tx * 5 + j]);

    #pragma unroll
    for (int i = 0; i < 4; i++)
        #pragma unroll
        for (int j = 0; j < 5; j++)
            s_log[(ty * 4 + i) * 41 + tx * 5 + j] = acc[i][j] + bias_r[j];
    __syncthreads();

    if (tid < 128) {
        float m = -INFINITY;
        #pragma unroll
        for (int c = 0; c < NCLSK; c++) m = fmaxf(m, s_log[tid * 41 + c]);
        float s = 0.f;
        #pragma unroll
        for (int c = 0; c < NCLSK; c++) s += __expf(s_log[tid * 41 + c] - m);
        s_lse[tid] = m + __logf(s);
    }
    __syncthreads();

    int rows = n - row0;
    if (rows > 128) rows = 128;
    int total = rows * NCLSK;
    for (int idx = tid; idx < total; idx += 256) {
        int r = idx / NCLSK;
        int c = idx - r * NCLSK;
        outb[(size_t)(row0 + r) * NCLSK + c] = s_log[r * 41 + c] - s_lse[r];
    }
}

// ---------------- launch ----------------
extern "C" void kernel_launch(void* const* d_in, const int* in_sizes, int n_in,
                              void* d_out, int out_size) {
    const float* x  = (const float*)d_in[0];
    const int*   ei = (const int*)d_in[1];     // int32 (JAX x64 disabled)
    const float* W0 = (const float*)d_in[2];
    const float* b0 = (const float*)d_in[3];
    const float* g0 = (const float*)d_in[4];
    const float* be0 = (const float*)d_in[5];
    const float* W1 = (const float*)d_in[6];
    const float* b1 = (const float*)d_in[7];
    const float* g1 = (const float*)d_in[8];
    const float* be1 = (const float*)d_in[9];
    const float* Wc = (const float*)d_in[10];
    const float* bc = (const float*)d_in[11];
    float* out = (float*)d_out;

    int n  = in_sizes[0] / F;
    int ne = in_sizes[1] / 2;

    void *p_h0, *p_h1, *p_deg, *p_stats;
    cudaGetSymbolAddress(&p_h0, g_hlin0);
    cudaGetSymbolAddress(&p_h1, g_hlin1);
    cudaGetSymbolAddress(&p_deg, g_deg);
    cudaGetSymbolAddress(&p_stats, g_stats);
    float* h0     = (float*)p_h0;
    float* h1     = (float*)p_h1;
    float* stats0 = (float*)p_stats;
    float* stats1 = stats0 + 2 * F;

    // CSR build (shared by both conv layers)
    cudaMemsetAsync(p_deg, 0, (size_t)n * sizeof(int));
    hist_kernel<<<(ne + 255) / 256, 256>>>(ei, ne, n);
    scan_blocks_kernel<<<(n + 255) / 256, 256>>>(n);
    fill_kernel<<<(ne + 255) / 256, 256>>>(ei, ne, n);

    int fused_blocks = (n + FBM - 1) / FBM;
    int cls_blocks   = (n + 127) / 128;

    // ---- layer 0: gather(x) -> GEMM(W0) -> hlin0 + stats0 ----
    fused_layer_kernel<0><<<fused_blocks, 256>>>(x, W0, b0, h0, stats0,
                                                 stats0, g0, be0, n);
    // ---- layer 1: gather(BN0+ReLU(hlin0)) -> GEMM(W1) -> hlin1 + stats1 ----
    fused_layer_kernel<1><<<fused_blocks, 256>>>(h0, W1, b1, h1, stats1,
                                                 stats0, g0, be0, n);
    // ---- classifier: fused BN1+ReLU + GEMM + log_softmax ----
    classifier_kernel<<<cls_blocks, 256>>>(h1, Wc, bc, g1, be1, out, n);
}

// round 8
// speedup vs baseline: 1.4202x; 1.4202x over previous
#include <cuda_runtime.h>
#include <math.h>

#define NMAX 50000
#define EMAX 600000
#define F    128
#define NCLSK 40
#define BN_EPS 1e-5f

typedef unsigned int uint32;

// ---------------- tf32 helpers ----------------
__device__ __forceinline__ uint32 tf32_of(float x) {
    uint32 r;
    asm("cvt.rna.tf32.f32 %0, %1;" : "=r"(r) : "f"(x));
    return r;
}
__device__ __forceinline__ void mma_tf32(float d[4],
                                         uint32 a0, uint32 a1, uint32 a2, uint32 a3,
                                         uint32 b0, uint32 b1) {
    asm("mma.sync.aligned.m16n8k8.row.col.f32.tf32.tf32.f32 "
        "{%0,%1,%2,%3}, {%4,%5,%6,%7}, {%8,%9}, {%0,%1,%2,%3};"
        : "+f"(d[0]), "+f"(d[1]), "+f"(d[2]), "+f"(d[3])
        : "r"(a0), "r"(a1), "r"(a2), "r"(a3), "r"(b0), "r"(b1));
}

// ---------------- scratch (device globals; no allocation allowed) ----------------
__device__ float  g_aggbuf[NMAX * F];   // aggregation output (GEMM input)
__device__ float  g_hlin0 [NMAX * F];   // layer-0 GEMM output
__device__ float  g_hlin1 [NMAX * F];   // layer-1 GEMM output
__device__ int    g_deg [NMAX];
__device__ int    g_off [NMAX];
__device__ int    g_cur [NMAX];
__device__ int    g_csrc[EMAX];
__device__ float  g_invdeg[NMAX];
__device__ float  g_stats[4 * F];   // layer0: [0..255], layer1: [256..511]
__device__ int    g_counter;

// ---------------- histogram (+ zero stats/counter piggyback) ----------------
__global__ void hist_kernel(const int* __restrict__ ei, int ne, int n) {
    if (blockIdx.x == 0) {
        g_stats[threadIdx.x] = 0.f;
        g_stats[256 + threadIdx.x] = 0.f;
        if (threadIdx.x == 0) g_counter = 0;
    }
    int e = blockIdx.x * blockDim.x + threadIdx.x;
    if (e < ne) {
        int d = ei[ne + e];
        if ((unsigned)d < (unsigned)n) atomicAdd(&g_deg[d], 1);
    }
}

// ---------------- one-pass block scan with atomic base ----------------
__global__ __launch_bounds__(256) void scan_blocks_kernel(int n) {
    int tid = threadIdx.x;
    int i = blockIdx.x * 256 + tid;
    int v = (i < n) ? g_deg[i] : 0;

    int incl = v;
    #pragma unroll
    for (int o = 1; o < 32; o <<= 1) {
        int t = __shfl_up_sync(0xffffffffu, incl, o);
        if ((tid & 31) >= o) incl += t;
    }
    __shared__ int wsum[8];
    if ((tid & 31) == 31) wsum[tid >> 5] = incl;
    __syncthreads();
    if (tid < 8) {
        int w = wsum[tid];
        int s = w;
        #pragma unroll
        for (int o = 1; o < 8; o <<= 1) {
            int t = __shfl_up_sync(0x000000ffu, s, o);
            if (tid >= o) s += t;
        }
        wsum[tid] = s - w;
    }
    __syncthreads();
    incl += wsum[tid >> 5];

    __shared__ int base_s;
    if (tid == 255) base_s = atomicAdd(&g_counter, incl);
    __syncthreads();

    if (i < n) {
        int off = base_s + incl - v;
        g_off[i] = off;
        g_cur[i] = off;
        g_invdeg[i] = 1.0f / fmaxf((float)v, 1.0f);
    }
}

__global__ void fill_kernel(const int* __restrict__ ei, int ne, int n) {
    int e = blockIdx.x * blockDim.x + threadIdx.x;
    if (e < ne) {
        int d = ei[ne + e];
        int s = ei[e];
        if ((unsigned)d < (unsigned)n && (unsigned)s < (unsigned)n) {
            int p = atomicAdd(&g_cur[d], 1);
            g_csrc[p] = s;
        }
    }
}

// ---------------- mean aggregation: one warp per node (R6 proven) ----------
__global__ __launch_bounds__(256) void agg_kernel(const float* __restrict__ feat,
                                                  float* __restrict__ outb, int n) {
    int wid  = threadIdx.x >> 5;
    int lane = threadIdx.x & 31;
    int node = blockIdx.x * 8 + wid;
    if (node >= n) return;
    int beg = g_off[node];
    int end = beg + g_deg[node];
    float4 acc  = make_float4(0.f, 0.f, 0.f, 0.f);
    float4 acc2 = make_float4(0.f, 0.f, 0.f, 0.f);
    int e = beg;
    for (; e + 1 < end; e += 2) {
        int s0 = g_csrc[e], s1 = g_csrc[e + 1];
        float4 v0 = *(const float4*)(feat + (size_t)s0 * F + lane * 4);
        float4 v1 = *(const float4*)(feat + (size_t)s1 * F + lane * 4);
        acc.x  += v0.x; acc.y  += v0.y; acc.z  += v0.z; acc.w  += v0.w;
        acc2.x += v1.x; acc2.y += v1.y; acc2.z += v1.z; acc2.w += v1.w;
    }
    if (e < end) {
        int s0 = g_csrc[e];
        float4 v0 = *(const float4*)(feat + (size_t)s0 * F + lane * 4);
        acc.x += v0.x; acc.y += v0.y; acc.z += v0.z; acc.w += v0.w;
    }
    float inv = g_invdeg[node];
    acc.x = (acc.x + acc2.x) * inv; acc.y = (acc.y + acc2.y) * inv;
    acc.z = (acc.z + acc2.z) * inv; acc.w = (acc.w + acc2.w) * inv;
    *(float4*)(outb + (size_t)node * F + lane * 4) = acc;
}

// --- mean aggregation with BN+ReLU per-edge; computes scale/shift itself ---
__global__ __launch_bounds__(256) void agg_bn_kernel(const float* __restrict__ feat,
                                                     const float* __restrict__ g,
                                                     const float* __restrict__ be,
                                                     float* __restrict__ outb, int n) {
    __shared__ float s_sc[F], s_sh[F];
    int tid = threadIdx.x;
    if (tid < F) {
        float mean = g_stats[tid] / (float)n;
        float var  = g_stats[F + tid] / (float)n - mean * mean;
        float sck = g[tid] * rsqrtf(var + BN_EPS);
        s_sc[tid] = sck;
        s_sh[tid] = be[tid] - mean * sck;
    }
    __syncthreads();

    int wid  = tid >> 5;
    int lane = tid & 31;
    int node = blockIdx.x * 8 + wid;
    if (node >= n) return;
    float4 sc = *(const float4*)&s_sc[lane * 4];
    float4 sh = *(const float4*)&s_sh[lane * 4];
    int beg = g_off[node];
    int end = beg + g_deg[node];
    float4 acc  = make_float4(0.f, 0.f, 0.f, 0.f);
    float4 acc2 = make_float4(0.f, 0.f, 0.f, 0.f);
    int e = beg;
    for (; e + 1 < end; e += 2) {
        int s0 = g_csrc[e], s1 = g_csrc[e + 1];
        float4 v0 = *(const float4*)(feat + (size_t)s0 * F + lane * 4);
        float4 v1 = *(const float4*)(feat + (size_t)s1 * F + lane * 4);
        acc.x  += fmaxf(v0.x * sc.x + sh.x, 0.f);
        acc.y  += fmaxf(v0.y * sc.y + sh.y, 0.f);
        acc.z  += fmaxf(v0.z * sc.z + sh.z, 0.f);
        acc.w  += fmaxf(v0.w * sc.w + sh.w, 0.f);
        acc2.x += fmaxf(v1.x * sc.x + sh.x, 0.f);
        acc2.y += fmaxf(v1.y * sc.y + sh.y, 0.f);
        acc2.z += fmaxf(v1.z * sc.z + sh.z, 0.f);
        acc2.w += fmaxf(v1.w * sc.w + sh.w, 0.f);
    }
    if (e < end) {
        int s0 = g_csrc[e];
        float4 v0 = *(const float4*)(feat + (size_t)s0 * F + lane * 4);
        acc.x += fmaxf(v0.x * sc.x + sh.x, 0.f);
        acc.y += fmaxf(v0.y * sc.y + sh.y, 0.f);
        acc.z += fmaxf(v0.z * sc.z + sh.z, 0.f);
        acc.w += fmaxf(v0.w * sc.w + sh.w, 0.f);
    }
    float inv = g_invdeg[node];
    acc.x = (acc.x + acc2.x) * inv; acc.y = (acc.y + acc2.y) * inv;
    acc.z = (acc.z + acc2.z) * inv; acc.w = (acc.w + acc2.w) * inv;
    *(float4*)(outb + (size_t)node * F + lane * 4) = acc;
}

// -------- TF32 tensor-core GEMM (128x128 tile) + fused BN-stats epilogue ----
#define APAD 132
#define BS_STRIDE 132
#define BS_BUF (8 * BS_STRIDE)
#define GEMM_SMEM_FLOATS (128 * APAD + 2 * BS_BUF + 2 * F)
__global__ __launch_bounds__(256, 2) void gemm_tf32_stats_kernel(
        const float* __restrict__ A,
        const float* __restrict__ W,
        const float* __restrict__ bias,
        float* __restrict__ C,
        float* __restrict__ stats, int n) {
    extern __shared__ float smem[];
    float* As    = smem;                      // [128][132] tf32-converted A
    float* Bs    = smem + 128 * APAD;         // [2][8][132] tf32-converted W chunk
    float* s_sum = smem + 128 * APAD + 2 * BS_BUF;
    float* s_sq  = s_sum + F;

    int tid = threadIdx.x;
    int block_row = blockIdx.x * 128;

    if (tid < F) { s_sum[tid] = 0.f; s_sq[tid] = 0.f; }

    // ---- load + convert full A tile (128 rows x 128 k) ----
    #pragma unroll
    for (int it = 0; it < 16; it++) {
        int i = it * 256 + tid;            // float4 index over the tile
        int row = i >> 5;
        int q = (i & 31) * 4;
        int grow = block_row + row;
        float4 v = make_float4(0.f, 0.f, 0.f, 0.f);
        if (grow < n) v = __ldg((const float4*)(A + (size_t)grow * F + q));
        float4 o;
        o.x = __uint_as_float(tf32_of(v.x));
        o.y = __uint_as_float(tf32_of(v.y));
        o.z = __uint_as_float(tf32_of(v.z));
        o.w = __uint_as_float(tf32_of(v.w));
        *(float4*)&As[row * APAD + q] = o;
    }

    // ---- prologue: W chunk 0 ----
    int bk = tid >> 5;
    int bc = (tid & 31) * 4;
    {
        float4 w = __ldg((const float4*)(W + (size_t)bk * F + bc));
        float4 o;
        o.x = __uint_as_float(tf32_of(w.x));
        o.y = __uint_as_float(tf32_of(w.y));
        o.z = __uint_as_float(tf32_of(w.z));
        o.w = __uint_as_float(tf32_of(w.w));
        *(float4*)&Bs[bk * BS_STRIDE + bc] = o;
    }
    __syncthreads();

    int wid = tid >> 5, lane = tid & 31;
    int wr = (wid & 3) * 32;        // warp row base within tile
    int wc = (wid >> 2) * 64;       // warp col base
    int qr = lane >> 2;             // 0..7
    int qc = lane & 3;              // 0..3

    float d[2][8][4];
    #pragma unroll
    for (int mt = 0; mt < 2; mt++)
        #pragma unroll
        for (int nt = 0; nt < 8; nt++)
            #pragma unroll
            for (int k = 0; k < 4; k++) d[mt][nt][k] = 0.f;

    int buf = 0;
    #pragma unroll
    for (int ks = 0; ks < 16; ks++) {
        float4 nw;
        bool more = ks < 15;
        if (more) nw = __ldg((const float4*)(W + (size_t)((ks + 1) * 8 + bk) * F + bc));

        int kb = ks * 8;
        uint32 afr[2][4];
        #pragma unroll
        for (int mt = 0; mt < 2; mt++) {
            int ar = wr + mt * 16 + qr;
            afr[mt][0] = __float_as_uint(As[ar * APAD + kb + qc]);
            afr[mt][1] = __float_as_uint(As[(ar + 8) * APAD + kb + qc]);
            afr[mt][2] = __float_as_uint(As[ar * APAD + kb + qc + 4]);
            afr[mt][3] = __float_as_uint(As[(ar + 8) * APAD + kb + qc + 4]);
        }
        const float* bp = Bs + buf * BS_BUF;
        #pragma unroll
        for (int nt = 0; nt < 8; nt++) {
            int bn = wc + nt * 8 + qr;
            uint32 b0 = __float_as_uint(bp[qc * BS_STRIDE + bn]);
            uint32 b1 = __float_as_uint(bp[(qc + 4) * BS_STRIDE + bn]);
            mma_tf32(d[0][nt], afr[0][0], afr[0][1], afr[0][2], afr[0][3], b0, b1);
            mma_tf32(d[1][nt], afr[1][0], afr[1][1], afr[1][2], afr[1][3], b0, b1);
        }
        if (more) {
            float* np = Bs + (buf ^ 1) * BS_BUF;
            float4 o;
            o.x = __uint_as_float(tf32_of(nw.x));
            o.y = __uint_as_float(tf32_of(nw.y));
            o.z = __uint_as_float(tf32_of(nw.z));
            o.w = __uint_as_float(tf32_of(nw.w));
            *(float4*)&np[bk * BS_STRIDE + bc] = o;
        }
        __syncthreads();
        buf ^= 1;
    }

    // ---- epilogue: bias + C write + BN stats ----
    #pragma unroll
    for (int nt = 0; nt < 8; nt++) {
        int col = wc + nt * 8 + qc * 2;
        float b0v = __ldg(&bias[col]);
        float b1v = __ldg(&bias[col + 1]);
        float s0 = 0.f, q0 = 0.f, s1 = 0.f, q1 = 0.f;
        #pragma unroll
        for (int mt = 0; mt < 2; mt++) {
            int r0 = block_row + wr + mt * 16 + qr;
            int r1 = r0 + 8;
            float v00 = d[mt][nt][0] + b0v;
            float v01 = d[mt][nt][1] + b1v;
            float v10 = d[mt][nt][2] + b0v;
            float v11 = d[mt][nt][3] + b1v;
            if (r0 < n) {
                *(float2*)(C + (size_t)r0 * F + col) = make_float2(v00, v01);
                s0 += v00; q0 += v00 * v00;
                s1 += v01; q1 += v01 * v01;
            }
            if (r1 < n) {
                *(float2*)(C + (size_t)r1 * F + col) = make_float2(v10, v11);
                s0 += v10; q0 += v10 * v10;
                s1 += v11; q1 += v11 * v11;
            }
        }
        atomicAdd(&s_sum[col], s0);
        atomicAdd(&s_sq[col], q0);
        atomicAdd(&s_sum[col + 1], s1);
        atomicAdd(&s_sq[col + 1], q1);
    }
    __syncthreads();
    if (tid < F) {
        atomicAdd(&stats[tid], s_sum[tid]);
        atomicAdd(&stats[F + tid], s_sq[tid]);
    }
}

// --- classifier: fused BN(from raw stats)+ReLU + GEMM + log_softmax --------
__global__ __launch_bounds__(256) void classifier_kernel(const float* __restrict__ H,
                                                         const float* __restrict__ Wc,
                                                         const float* __restrict__ bc,
                                                         const float* __restrict__ g,
                                                         const float* __restrict__ be,
                                                         float* __restrict__ outb, int n) {
    __shared__ float sbuf[6656];
    float* As    = sbuf;           // [8][128]  during k-loop
    float* Ws    = sbuf + 1024;    // [128][40]
    float* s_log = sbuf;           // overlay after k-loop: [128][41]
    float* s_lse = sbuf + 5248;    // [128]
    float* s_sc  = sbuf + 6144;    // [128]
    float* s_sh  = sbuf + 6272;    // [128]

    int tid = threadIdx.x;
    int row0 = blockIdx.x * 128;

    if (tid < F) {
        float mean = g_stats[2 * F + tid] / (float)n;
        float var  = g_stats[3 * F + tid] / (float)n - mean * mean;
        float sck = g[tid] * rsqrtf(var + BN_EPS);
        s_sc[tid] = sck;
        s_sh[tid] = be[tid] - mean * sck;
    }
    for (int idx = tid; idx < F * NCLSK; idx += 256) Ws[idx] = Wc[idx];

    int tx = tid & 7;
    int ty = tid >> 3;

    float acc[4][5];
    #pragma unroll
    for (int i = 0; i < 4; i++)
        #pragma unroll
        for (int j = 0; j < 5; j++) acc[i][j] = 0.f;

    int lrow = tid >> 1;
    int seg  = (tid & 1) * 4;
    int grow = row0 + lrow;
    bool rok = grow < n;
    const float* hp = H + (size_t)grow * F;
    __syncthreads();

    for (int k0 = 0; k0 < F; k0 += 8) {
        float4 v = make_float4(0.f,0.f,0.f,0.f);
        if (rok) v = *(const float4*)(hp + k0 + seg);
        float4 sc = *(const float4*)&s_sc[k0 + seg];
        float4 sh = *(const float4*)&s_sh[k0 + seg];
        v.x = fmaxf(v.x * sc.x + sh.x, 0.f);
        v.y = fmaxf(v.y * sc.y + sh.y, 0.f);
        v.z = fmaxf(v.z * sc.z + sh.z, 0.f);
        v.w = fmaxf(v.w * sc.w + sh.w, 0.f);
        As[(seg + 0) * 128 + lrow] = v.x;
        As[(seg + 1) * 128 + lrow] = v.y;
        As[(seg + 2) * 128 + lrow] = v.z;
        As[(seg + 3) * 128 + lrow] = v.w;
        __syncthreads();
        #pragma unroll
        for (int kk = 0; kk < 8; kk++) {
            float ra[4], rb[5];
            #pragma unroll
            for (int i = 0; i < 4; i++) ra[i] = As[kk * 128 + ty * 4 + i];
            #pragma unroll
            for (int j = 0; j < 5; j++) rb[j] = Ws[(k0 + kk) * NCLSK + tx * 5 + j];
            #pragma unroll
            for (int i = 0; i < 4; i++)
                #pragma unroll
                for (int j = 0; j < 5; j++) acc[i][j] += ra[i] * rb[j];
        }
        __syncthreads();
    }

    float bias_r[5];
    #pragma unroll
    for (int j = 0; j < 5; j++) bias_r[j] = __ldg(&bc[tx * 5 + j]);

    #pragma unroll
    for (int i = 0; i < 4; i++)
        #pragma unroll
        for (int j = 0; j < 5; j++)
            s_log[(ty * 4 + i) * 41 + tx * 5 + j] = acc[i][j] + bias_r[j];
    __syncthreads();

    if (tid < 128) {
        float m = -INFINITY;
        #pragma unroll
        for (int c = 0; c < NCLSK; c++) m = fmaxf(m, s_log[tid * 41 + c]);
        float s = 0.f;
        #pragma unroll
        for (int c = 0; c < NCLSK; c++) s += __expf(s_log[tid * 41 + c] - m);
        s_lse[tid] = m + __logf(s);
    }
    __syncthreads();

    int rows = n - row0;
    if (rows > 128) rows = 128;
    int total = rows * NCLSK;
    for (int idx = tid; idx < total; idx += 256) {
        int r = idx / NCLSK;
        int c = idx - r * NCLSK;
        outb[(size_t)(row0 + r) * NCLSK + c] = s_log[r * 41 + c] - s_lse[r];
    }
}

// ---------------- launch ----------------
extern "C" void kernel_launch(void* const* d_in, const int* in_sizes, int n_in,
                              void* d_out, int out_size) {
    const float* x  = (const float*)d_in[0];
    const int*   ei = (const int*)d_in[1];     // int32 (JAX x64 disabled)
    const float* W0 = (const float*)d_in[2];
    const float* b0 = (const float*)d_in[3];
    const float* g0 = (const float*)d_in[4];
    const float* be0 = (const float*)d_in[5];
    const float* W1 = (const float*)d_in[6];
    const float* b1 = (const float*)d_in[7];
    const float* g1 = (const float*)d_in[8];
    const float* be1 = (const float*)d_in[9];
    const float* Wc = (const float*)d_in[10];
    const float* bc = (const float*)d_in[11];
    float* out = (float*)d_out;

    int n  = in_sizes[0] / F;
    int ne = in_sizes[1] / 2;

    void *p_agg, *p_h0, *p_h1, *p_deg, *p_stats;
    cudaGetSymbolAddress(&p_agg, g_aggbuf);
    cudaGetSymbolAddress(&p_h0, g_hlin0);
    cudaGetSymbolAddress(&p_h1, g_hlin1);
    cudaGetSymbolAddress(&p_deg, g_deg);
    cudaGetSymbolAddress(&p_stats, g_stats);
    float* aggp   = (float*)p_agg;
    float* h0     = (float*)p_h0;
    float* h1     = (float*)p_h1;
    float* stats0 = (float*)p_stats;
    float* stats1 = stats0 + 2 * F;

    cudaFuncSetAttribute(gemm_tf32_stats_kernel,
                         cudaFuncAttributeMaxDynamicSharedMemorySize,
                         GEMM_SMEM_FLOATS * (int)sizeof(float));

    // CSR build (shared by both conv layers)
    cudaMemsetAsync(p_deg, 0, (size_t)n * sizeof(int));
    hist_kernel<<<(ne + 255) / 256, 256>>>(ei, ne, n);
    scan_blocks_kernel<<<(n + 255) / 256, 256>>>(n);
    fill_kernel<<<(ne + 255) / 256, 256>>>(ei, ne, n);

    int agg_blocks  = (n + 7) / 8;
    int gemm_blocks = (n + 127) / 128;
    int gemm_smem   = GEMM_SMEM_FLOATS * (int)sizeof(float);

    // ---- layer 0 ----
    agg_kernel<<<agg_blocks, 256>>>(x, aggp, n);
    gemm_tf32_stats_kernel<<<gemm_blocks, 256, gemm_smem>>>(aggp, W0, b0, h0, stats0, n);

    // ---- layer 1 (BN+ReLU of layer 0 fused into the gather) ----
    agg_bn_kernel<<<agg_blocks, 256>>>(h0, g0, be0, aggp, n);
    gemm_tf32_stats_kernel<<<gemm_blocks, 256, gemm_smem>>>(aggp, W1, b1, h1, stats1, n);

    // ---- classifier: fused BN1+ReLU + GEMM + log_softmax ----
    classifier_kernel<<<gemm_blocks, 256>>>(h1, Wc, bc, g1, be1, out, n);
}

// round 9
// speedup vs baseline: 1.4863x; 1.0466x over previous
#include <cuda_runtime.h>
#include <cuda_fp16.h>
#include <math.h>

#define NMAX 50000
#define EMAX 600000
#define F    128
#define NCLSK 40
#define BN_EPS 1e-5f

typedef unsigned long long u64;
typedef unsigned int uint32;

__device__ __forceinline__ u64 pack_dup(float a) {
    u64 r;
    asm("mov.b64 %0, {%1, %1};" : "=l"(r) : "f"(a));
    return r;
}
__device__ __forceinline__ void ffma2(u64 &d, u64 a, u64 b) {
    asm("fma.rn.f32x2 %0, %1, %2, %0;" : "+l"(d) : "l"(a), "l"(b));
}
__device__ __forceinline__ float2 unpack2(u64 v) {
    float lo, hi;
    asm("mov.b64 {%0, %1}, %2;" : "=f"(lo), "=f"(hi) : "l"(v));
    return make_float2(lo, hi);
}

// ---------------- scratch (device globals; no allocation allowed) ----------------
__device__ float  g_aggbuf[NMAX * F];   // fp32 aggregation output (GEMM input)
__device__ float  g_hlin0 [NMAX * F];   // layer-0 GEMM output
__device__ float  g_hlin1 [NMAX * F];   // layer-1 GEMM output
__device__ uint2  g_feath [NMAX * 32];  // fp16 feature rows (128 halves = 32 uint2)
__device__ int    g_deg [NMAX];
__device__ int    g_off [NMAX];
__device__ int    g_cur [NMAX];
__device__ int    g_csrc[EMAX];
__device__ float  g_invdeg[NMAX];
__device__ float  g_stats[4 * F];   // layer0: [0..255], layer1: [256..511]
__device__ int    g_counter;

// ---------------- fp32 -> fp16 feature conversion ----------------
__global__ __launch_bounds__(256) void convert_x_kernel(const float4* __restrict__ x,
                                                        int total4) {
    int i = blockIdx.x * 256 + threadIdx.x;
    if (i < total4) {
        float4 v = __ldg(&x[i]);
        __half2 h01 = __floats2half2_rn(v.x, v.y);
        __half2 h23 = __floats2half2_rn(v.z, v.w);
        uint2 r;
        r.x = *(uint32*)&h01;
        r.y = *(uint32*)&h23;
        g_feath[i] = r;
    }
}

// ---- node-wise BN+ReLU on h (fp32) -> fp16 features for the next gather ----
__global__ __launch_bounds__(256) void bnrelu_h_kernel(const float4* __restrict__ h,
                                                       const float* __restrict__ stats,
                                                       const float* __restrict__ g,
                                                       const float* __restrict__ be,
                                                       int n, int total4) {
    __shared__ float s_sc[F], s_sh[F];
    int tid = threadIdx.x;
    if (tid < F) {
        float mean = stats[tid] / (float)n;
        float var  = stats[F + tid] / (float)n - mean * mean;
        float sck = g[tid] * rsqrtf(var + BN_EPS);
        s_sc[tid] = sck;
        s_sh[tid] = be[tid] - mean * sck;
    }
    __syncthreads();
    int i = blockIdx.x * 256 + tid;
    if (i < total4) {
        int c4 = (i & 31) * 4;
        float4 v = __ldg(&h[i]);
        float4 sc = *(const float4*)&s_sc[c4];
        float4 sh = *(const float4*)&s_sh[c4];
        v.x = fmaxf(v.x * sc.x + sh.x, 0.f);
        v.y = fmaxf(v.y * sc.y + sh.y, 0.f);
        v.z = fmaxf(v.z * sc.z + sh.z, 0.f);
        v.w = fmaxf(v.w * sc.w + sh.w, 0.f);
        __half2 h01 = __floats2half2_rn(v.x, v.y);
        __half2 h23 = __floats2half2_rn(v.z, v.w);
        uint2 r;
        r.x = *(uint32*)&h01;
        r.y = *(uint32*)&h23;
        g_feath[i] = r;
    }
}

// ---------------- histogram (+ zero stats/counter piggyback) ----------------
__global__ void hist_kernel(const int* __restrict__ ei, int ne, int n) {
    if (blockIdx.x == 0) {
        g_stats[threadIdx.x] = 0.f;
        g_stats[256 + threadIdx.x] = 0.f;
        if (threadIdx.x == 0) g_counter = 0;
    }
    int e = blockIdx.x * blockDim.x + threadIdx.x;
    if (e < ne) {
        int d = ei[ne + e];
        if ((unsigned)d < (unsigned)n) atomicAdd(&g_deg[d], 1);
    }
}

// ---------------- one-pass block scan with atomic base ----------------
__global__ __launch_bounds__(256) void scan_blocks_kernel(int n) {
    int tid = threadIdx.x;
    int i = blockIdx.x * 256 + tid;
    int v = (i < n) ? g_deg[i] : 0;

    int incl = v;
    #pragma unroll
    for (int o = 1; o < 32; o <<= 1) {
        int t = __shfl_up_sync(0xffffffffu, incl, o);
        if ((tid & 31) >= o) incl += t;
    }
    __shared__ int wsum[8];
    if ((tid & 31) == 31) wsum[tid >> 5] = incl;
    __syncthreads();
    if (tid < 8) {
        int w = wsum[tid];
        int s = w;
        #pragma unroll
        for (int o = 1; o < 8; o <<= 1) {
            int t = __shfl_up_sync(0x000000ffu, s, o);
            if (tid >= o) s += t;
        }
        wsum[tid] = s - w;
    }
    __syncthreads();
    incl += wsum[tid >> 5];

    __shared__ int base_s;
    if (tid == 255) base_s = atomicAdd(&g_counter, incl);
    __syncthreads();

    if (i < n) {
        int off = base_s + incl - v;
        g_off[i] = off;
        g_cur[i] = off;
        g_invdeg[i] = 1.0f / fmaxf((float)v, 1.0f);
    }
}

__global__ void fill_kernel(const int* __restrict__ ei, int ne, int n) {
    int e = blockIdx.x * blockDim.x + threadIdx.x;
    if (e < ne) {
        int d = ei[ne + e];
        int s = ei[e];
        if ((unsigned)d < (unsigned)n && (unsigned)s < (unsigned)n) {
            int p = atomicAdd(&g_cur[d], 1);
            g_csrc[p] = s;
        }
    }
}

// ------ mean aggregation over fp16 rows: one warp per node, fp32 accum ------
__global__ __launch_bounds__(256) void agg_h_kernel(float* __restrict__ outb, int n) {
    int wid  = threadIdx.x >> 5;
    int lane = threadIdx.x & 31;
    int node = blockIdx.x * 8 + wid;
    if (node >= n) return;
    int beg = g_off[node];
    int end = beg + g_deg[node];
    float4 acc  = make_float4(0.f, 0.f, 0.f, 0.f);
    float4 acc2 = make_float4(0.f, 0.f, 0.f, 0.f);
    int e = beg;
    for (; e + 1 < end; e += 2) {
        int s0 = g_csrc[e], s1 = g_csrc[e + 1];
        uint2 r0 = __ldg(&g_feath[(size_t)s0 * 32 + lane]);
        uint2 r1 = __ldg(&g_feath[(size_t)s1 * 32 + lane]);
        float2 p0 = __half22float2(*(__half2*)&r0.x);
        float2 p1 = __half22float2(*(__half2*)&r0.y);
        float2 q0 = __half22float2(*(__half2*)&r1.x);
        float2 q1 = __half22float2(*(__half2*)&r1.y);
        acc.x  += p0.x; acc.y  += p0.y; acc.z  += p1.x; acc.w  += p1.y;
        acc2.x += q0.x; acc2.y += q0.y; acc2.z += q1.x; acc2.w += q1.y;
    }
    if (e < end) {
        int s0 = g_csrc[e];
        uint2 r0 = __ldg(&g_feath[(size_t)s0 * 32 + lane]);
        float2 p0 = __half22float2(*(__half2*)&r0.x);
        float2 p1 = __half22float2(*(__half2*)&r0.y);
        acc.x += p0.x; acc.y += p0.y; acc.z += p1.x; acc.w += p1.y;
    }
    float inv = g_invdeg[node];
    acc.x = (acc.x + acc2.x) * inv; acc.y = (acc.y + acc2.y) * inv;
    acc.z = (acc.z + acc2.z) * inv; acc.w = (acc.w + acc2.w) * inv;
    *(float4*)(outb + (size_t)node * F + lane * 4) = acc;
}

// -------- SGEMM (R6 proven: double-buffered, pack_dup f32x2) + stats --------
#define GBM 128
#define GBK 8
__global__ __launch_bounds__(256) void gemm_stats_kernel(const float* __restrict__ A,
                                                         const float* __restrict__ W,
                                                         const float* __restrict__ bias,
                                                         float* __restrict__ C,
                                                         float* __restrict__ stats, int n) {
    __shared__ float As[2][GBK][GBM];
    __shared__ float Bs[2][GBK][F];
    __shared__ float s_sum[F];
    __shared__ float s_sq[F];

    int block_row = blockIdx.x * GBM;
    int tid = threadIdx.x;
    int tx = tid & 15, ty = tid >> 4;

    int a_row = tid >> 1;
    int a_k   = (tid & 1) * 4;
    int b_k   = tid >> 5;
    int b_col = (tid & 31) * 4;

    int grow = block_row + a_row;
    bool arow_ok = grow < n;
    const float* aptr = A + (size_t)grow * F + a_k;

    u64 acc2[8][4];
    #pragma unroll
    for (int i = 0; i < 8; i++)
        #pragma unroll
        for (int j = 0; j < 4; j++) acc2[i][j] = 0ULL;

    float4 av = arow_ok ? *(const float4*)aptr : make_float4(0.f,0.f,0.f,0.f);
    float4 bv = *(const float4*)(W + (size_t)b_k * F + b_col);
    As[0][a_k + 0][a_row] = av.x;
    As[0][a_k + 1][a_row] = av.y;
    As[0][a_k + 2][a_row] = av.z;
    As[0][a_k + 3][a_row] = av.w;
    *(float4*)&Bs[0][b_k][b_col] = bv;
    __syncthreads();

    int buf = 0;
    #pragma unroll
    for (int k0 = 0; k0 < F; k0 += GBK) {
        float4 nav, nbv;
        bool more = (k0 + GBK) < F;
        if (more) {
            nav = arow_ok ? *(const float4*)(aptr + k0 + GBK)
                          : make_float4(0.f,0.f,0.f,0.f);
            nbv = *(const float4*)(W + (size_t)(k0 + GBK + b_k) * F + b_col);
        }
        #pragma unroll
        for (int kk = 0; kk < GBK; kk++) {
            float4 a0 = *(const float4*)&As[buf][kk][ty * 8];
            float4 a1 = *(const float4*)&As[buf][kk][ty * 8 + 4];
            ulonglong2 b01 = *(const ulonglong2*)&Bs[buf][kk][tx * 8];
            ulonglong2 b23 = *(const ulonglong2*)&Bs[buf][kk][tx * 8 + 4];
            u64 rb[4] = {b01.x, b01.y, b23.x, b23.y};
            u64 ra[8] = {pack_dup(a0.x), pack_dup(a0.y), pack_dup(a0.z), pack_dup(a0.w),
                         pack_dup(a1.x), pack_dup(a1.y), pack_dup(a1.z), pack_dup(a1.w)};
            #pragma unroll
            for (int i = 0; i < 8; i++)
                #pragma unroll
                for (int j = 0; j < 4; j++) ffma2(acc2[i][j], ra[i], rb[j]);
        }
        if (more) {
            int nb = buf ^ 1;
            As[nb][a_k + 0][a_row] = nav.x;
            As[nb][a_k + 1][a_row] = nav.y;
            As[nb][a_k + 2][a_row] = nav.z;
            As[nb][a_k + 3][a_row] = nav.w;
            *(float4*)&Bs[nb][b_k][b_col] = nbv;
        }
        __syncthreads();
        buf ^= 1;
    }

    float bias_r[8];
    #pragma unroll
    for (int j = 0; j < 8; j++) bias_r[j] = __ldg(&bias[tx * 8 + j]);

    if (tid < F) { s_sum[tid] = 0.f; s_sq[tid] = 0.f; }
    __syncthreads();

    float ps[8], pq[8];
    #pragma unroll
    for (int j = 0; j < 8; j++) { ps[j] = 0.f; pq[j] = 0.f; }

    #pragma unroll
    for (int i = 0; i < 8; i++) {
        int r = block_row + ty * 8 + i;
        if (r < n) {
            float va[8];
            #pragma unroll
            for (int jp = 0; jp < 4; jp++) {
                float2 p = unpack2(acc2[i][jp]);
                va[jp * 2 + 0] = p.x + bias_r[jp * 2 + 0];
                va[jp * 2 + 1] = p.y + bias_r[jp * 2 + 1];
            }
            #pragma unroll
            for (int j = 0; j < 8; j += 4) {
                float4 o = make_float4(va[j], va[j+1], va[j+2], va[j+3]);
                *(float4*)(C + (size_t)r * F + tx * 8 + j) = o;
            }
            #pragma unroll
            for (int j = 0; j < 8; j++) { ps[j] += va[j]; pq[j] += va[j] * va[j]; }
        }
    }
    #pragma unroll
    for (int j = 0; j < 8; j++) {
        atomicAdd(&s_sum[tx * 8 + j], ps[j]);
        atomicAdd(&s_sq[tx * 8 + j], pq[j]);
    }
    __syncthreads();
    if (tid < F) {
        atomicAdd(&stats[tid], s_sum[tid]);
        atomicAdd(&stats[F + tid], s_sq[tid]);
    }
}

// --- classifier: fused BN(from raw stats)+ReLU + GEMM + log_softmax --------
__global__ __launch_bounds__(256) void classifier_kernel(const float* __restrict__ H,
                                                         const float* __restrict__ Wc,
                                                         const float* __restrict__ bc,
                                                         const float* __restrict__ g,
                                                         const float* __restrict__ be,
                                                         float* __restrict__ outb, int n) {
    __shared__ float sbuf[6656];
    float* As    = sbuf;           // [8][128]  during k-loop
    float* Ws    = sbuf + 1024;    // [128][40]
    float* s_log = sbuf;           // overlay after k-loop: [128][41]
    float* s_lse = sbuf + 5248;    // [128]
    float* s_sc  = sbuf + 6144;    // [128]
    float* s_sh  = sbuf + 6272;    // [128]

    int tid = threadIdx.x;
    int row0 = blockIdx.x * 128;

    if (tid < F) {
        float mean = g_stats[2 * F + tid] / (float)n;
        float var  = g_stats[3 * F + tid] / (float)n - mean * mean;
        float sck = g[tid] * rsqrtf(var + BN_EPS);
        s_sc[tid] = sck;
        s_sh[tid] = be[tid] - mean * sck;
    }
    for (int idx = tid; idx < F * NCLSK; idx += 256) Ws[idx] = Wc[idx];

    int tx = tid & 7;
    int ty = tid >> 3;

    float acc[4][5];
    #pragma unroll
    for (int i = 0; i < 4; i++)
        #pragma unroll
        for (int j = 0; j < 5; j++) acc[i][j] = 0.f;

    int lrow = tid >> 1;
    int seg  = (tid & 1) * 4;
    int grow = row0 + lrow;
    bool rok = grow < n;
    const float* hp = H + (size_t)grow * F;
    __syncthreads();

    for (int k0 = 0; k0 < F; k0 += 8) {
        float4 v = make_float4(0.f,0.f,0.f,0.f);
        if (rok) v = *(const float4*)(hp + k0 + seg);
        float4 sc = *(const float4*)&s_sc[k0 + seg];
        float4 sh = *(const float4*)&s_sh[k0 + seg];
        v.x = fmaxf(v.x * sc.x + sh.x, 0.f);
        v.y = fmaxf(v.y * sc.y + sh.y, 0.f);
        v.z = fmaxf(v.z * sc.z + sh.z, 0.f);
        v.w = fmaxf(v.w * sc.w + sh.w, 0.f);
        As[(seg + 0) * 128 + lrow] = v.x;
        As[(seg + 1) * 128 + lrow] = v.y;
        As[(seg + 2) * 128 + lrow] = v.z;
        As[(seg + 3) * 128 + lrow] = v.w;
        __syncthreads();
        #pragma unroll
        for (int kk = 0; kk < 8; kk++) {
            float ra[4], rb[5];
            #pragma unroll
            for (int i = 0; i < 4; i++) ra[i] = As[kk * 128 + ty * 4 + i];
            #pragma unroll
            for (int j = 0; j < 5; j++) rb[j] = Ws[(k0 + kk) * NCLSK + tx * 5 + j];
            #pragma unroll
            for (int i = 0; i < 4; i++)
                #pragma unroll
                for (int j = 0; j < 5; j++) acc[i][j] += ra[i] * rb[j];
        }
        __syncthreads();
    }

    float bias_r[5];
    #pragma unroll
    for (int j = 0; j < 5; j++) bias_r[j] = __ldg(&bc[tx * 5 + j]);

    #pragma unroll
    for (int i = 0; i < 4; i++)
        #pragma unroll
        for (int j = 0; j < 5; j++)
            s_log[(ty * 4 + i) * 41 + tx * 5 + j] = acc[i][j] + bias_r[j];
    __syncthreads();

    if (tid < 128) {
        float m = -INFINITY;
        #pragma unroll
        for (int c = 0; c < NCLSK; c++) m = fmaxf(m, s_log[tid * 41 + c]);
        float s = 0.f;
        #pragma unroll
        for (int c = 0; c < NCLSK; c++) s += __expf(s_log[tid * 41 + c] - m);
        s_lse[tid] = m + __logf(s);
    }
    __syncthreads();

    int rows = n - row0;
    if (rows > 128) rows = 128;
    int total = rows * NCLSK;
    for (int idx = tid; idx < total; idx += 256) {
        int r = idx / NCLSK;
        int c = idx - r * NCLSK;
        outb[(size_t)(row0 + r) * NCLSK + c] = s_log[r * 41 + c] - s_lse[r];
    }
}

// ---------------- launch ----------------
extern "C" void kernel_launch(void* const* d_in, const int* in_sizes, int n_in,
                              void* d_out, int out_size) {
    const float* x  = (const float*)d_in[0];
    const int*   ei = (const int*)d_in[1];     // int32 (JAX x64 disabled)
    const float* W0 = (const float*)d_in[2];
    const float* b0 = (const float*)d_in[3];
    const float* g0 = (const float*)d_in[4];
    const float* be0 = (const float*)d_in[5];
    const float* W1 = (const float*)d_in[6];
    const float* b1 = (const float*)d_in[7];
    const float* g1 = (const float*)d_in[8];
    const float* be1 = (const float*)d_in[9];
    const float* Wc = (const float*)d_in[10];
    const float* bc = (const float*)d_in[11];
    float* out = (float*)d_out;

    int n  = in_sizes[0] / F;
    int ne = in_sizes[1] / 2;

    void *p_agg, *p_h0, *p_h1, *p_deg, *p_stats;
    cudaGetSymbolAddress(&p_agg, g_aggbuf);
    cudaGetSymbolAddress(&p_h0, g_hlin0);
    cudaGetSymbolAddress(&p_h1, g_hlin1);
    cudaGetSymbolAddress(&p_deg, g_deg);
    cudaGetSymbolAddress(&p_stats, g_stats);
    float* aggp   = (float*)p_agg;
    float* h0     = (float*)p_h0;
    float* h1     = (float*)p_h1;
    float* stats0 = (float*)p_stats;
    float* stats1 = stats0 + 2 * F;

    int total4 = n * (F / 4);   // float4 / uint2 units per feature matrix

    // CSR build + fp16 conversion of x
    cudaMemsetAsync(p_deg, 0, (size_t)n * sizeof(int));
    convert_x_kernel<<<(total4 + 255) / 256, 256>>>((const float4*)x, total4);
    hist_kernel<<<(ne + 255) / 256, 256>>>(ei, ne, n);
    scan_blocks_kernel<<<(n + 255) / 256, 256>>>(n);
    fill_kernel<<<(ne + 255) / 256, 256>>>(ei, ne, n);

    int agg_blocks  = (n + 7) / 8;
    int gemm_blocks = (n + GBM - 1) / GBM;

    // ---- layer 0 ----
    agg_h_kernel<<<agg_blocks, 256>>>(aggp, n);
    gemm_stats_kernel<<<gemm_blocks, 256>>>(aggp, W0, b0, h0, stats0, n);

    // ---- layer 1: node-wise BN0+ReLU -> fp16, then gather ----
    bnrelu_h_kernel<<<(total4 + 255) / 256, 256>>>((const float4*)h0, stats0,
                                                   g0, be0, n, total4);
    agg_h_kernel<<<agg_blocks, 256>>>(aggp, n);
    gemm_stats_kernel<<<gemm_blocks, 256>>>(aggp, W1, b1, h1, stats1, n);

    // ---- classifier: fused BN1+ReLU + GEMM + log_softmax ----
    classifier_kernel<<<gemm_blocks, 256>>>(h1, Wc, bc, g1, be1, out, n);
}